// round 4
// baseline (speedup 1.0000x reference)
#include <cuda_runtime.h>
#include <cuda_bf16.h>

#define NB 2048
#define NT 256

// Zero-initialized at module load. The finalizing block resets them to zero
// after each run, so every graph replay starts from a clean state.
__device__ double       g_ce;
__device__ unsigned int g_cm[64];
__device__ unsigned int g_done;

__global__ void __launch_bounds__(NT)
fused_k(const float4* __restrict__ pred, const float4* __restrict__ gt,
        const float* __restrict__ cw, float* __restrict__ out,
        int B, double invB)
{
    __shared__ unsigned int cm_s[64];
    __shared__ float cw_s[8];
    __shared__ float warpsum[NT / 32];
    __shared__ unsigned int s_ticket;

    int t = threadIdx.x;
    if (t < 64) cm_s[t] = 0u;
    if (t < 8)  cw_s[t] = cw[t];
    __syncthreads();

    float ce = 0.0f;
    int stride = gridDim.x * blockDim.x;
    for (int i = blockIdx.x * blockDim.x + t; i < B; i += stride) {
        // batch all 4 128-bit loads up front (MLP=4 per iteration)
        float4 a0 = __ldg(&pred[2 * i]);
        float4 a1 = __ldg(&pred[2 * i + 1]);
        float4 g0 = __ldg(&gt[2 * i]);
        float4 g1 = __ldg(&gt[2 * i + 1]);
        float x[8]  = {a0.x, a0.y, a0.z, a0.w, a1.x, a1.y, a1.z, a1.w};
        float gv[8] = {g0.x, g0.y, g0.z, g0.w, g1.x, g1.y, g1.z, g1.w};

        // pred argmax (first-max tie-break = jnp.argmax; softmax is monotone)
        float m = x[0]; int pa = 0;
        #pragma unroll
        for (int j = 1; j < 8; j++) { if (x[j] > m) { m = x[j]; pa = j; } }

        // gt index from one-hot via fma dot with [0..7]
        float fg = gv[1];
        fg = fmaf(2.0f, gv[2], fg);
        fg = fmaf(3.0f, gv[3], fg);
        fg = fmaf(4.0f, gv[4], fg);
        fg = fmaf(5.0f, gv[5], fg);
        fg = fmaf(6.0f, gv[6], fg);
        fg = fmaf(7.0f, gv[7], fg);
        int gi = (int)(fg + 0.5f);

        // softmax without max-shift: x ~ N(0,1), |x| < ~7, EX2 range-safe
        float e[8];
        float S = 0.0f;
        #pragma unroll
        for (int j = 0; j < 8; j++) { e[j] = __expf(x[j]); S += e[j]; }

        float r = __fdividef(1.0f, S);

        // p[gi] via dot with one-hot (no dynamic register indexing)
        float eg = e[0] * gv[0];
        #pragma unroll
        for (int j = 1; j < 8; j++) eg = fmaf(e[j], gv[j], eg);
        float pg = eg * r;

        // S2 = sum_j exp(p_j), p_j in (0,1]
        float S2 = 0.0f;
        #pragma unroll
        for (int j = 0; j < 8; j++) S2 += __expf(e[j] * r);

        float lse2 = __logf(S2);

        ce = fmaf(cw_s[gi], lse2 - pg, ce);
        atomicAdd(&cm_s[gi * 8 + pa], 1u);
    }

    // CE reduction: warp shuffle -> shared -> one double atomic per block
    #pragma unroll
    for (int o = 16; o > 0; o >>= 1) ce += __shfl_down_sync(0xFFFFFFFFu, ce, o);
    if ((t & 31) == 0) warpsum[t >> 5] = ce;
    __syncthreads();
    if (t == 0) {
        double s = 0.0;
        #pragma unroll
        for (int k = 0; k < NT / 32; k++) s += (double)warpsum[k];
        atomicAdd(&g_ce, s);
    }
    if (t < 64) atomicAdd(&g_cm[t], cm_s[t]);

    // Last-block-done finalize (replaces the separate final kernel).
    __syncthreads();
    if (t == 0) {
        __threadfence();  // make this block's g_ce / g_cm atomics visible
        s_ticket = atomicAdd(&g_done, 1u);
    }
    __syncthreads();

    if (s_ticket == (unsigned)(gridDim.x - 1)) {
        if (t == 0) {
            // all blocks have flushed; safe to read, finalize, and reset
            unsigned int cm[64];
            #pragma unroll
            for (int k = 0; k < 64; k++)
                cm[k] = *((volatile unsigned int*)&g_cm[k]);
            double ce_tot = *((volatile double*)&g_ce);

            double dice_loss = 0.0;
            #pragma unroll
            for (int ii = 0; ii < 8; ii++) {
                double tp = (double)cm[ii * 8 + ii];
                double row = 0.0, col = 0.0;
                #pragma unroll
                for (int j = 0; j < 8; j++) {
                    row += (double)cm[ii * 8 + j];
                    col += (double)cm[j * 8 + ii];
                }
                double fp = col - tp, fn = row - tp;
                double dice = (tp + 1e-8) / (tp + fp + fn + 1e-8);
                dice_loss += (1.0 - dice) * (double)cw_s[ii];
            }
            dice_loss *= (1.0 / 8.0);
            out[0] = (float)(ce_tot * invB + 0.5 * dice_loss);

            // reset state for the next graph replay
            g_ce = 0.0;
            #pragma unroll
            for (int k = 0; k < 64; k++) g_cm[k] = 0u;
            __threadfence();
            g_done = 0u;
        }
    }
}

extern "C" void kernel_launch(void* const* d_in, const int* in_sizes, int n_in,
                              void* d_out, int out_size) {
    const float4* pred = (const float4*)d_in[0];
    const float4* gt   = (const float4*)d_in[1];
    const float*  cw   = (const float*)d_in[2];
    float* out = (float*)d_out;
    int B = in_sizes[0] / 8;

    fused_k<<<NB, NT>>>(pred, gt, cw, out, B, 1.0 / (double)B);
}

// round 5
// speedup vs baseline: 1.1333x; 1.1333x over previous
#include <cuda_runtime.h>
#include <cuda_bf16.h>

#define NB 2048
#define NT 256

// Zero-initialized at module load. The finalizing block resets them to zero
// after each run, so every graph replay starts from a clean state.
__device__ double       g_ce;
__device__ unsigned int g_cm[64];
__device__ unsigned int g_done;

__global__ void __launch_bounds__(NT, 4)   // cap regs at 64 -> 4 CTAs/SM, ~48% occ
fused_k(const float4* __restrict__ pred, const float4* __restrict__ gt,
        const float* __restrict__ cw, float* __restrict__ out,
        int B, double invB)
{
    __shared__ unsigned int cm_s[64];
    __shared__ float cw_s[8];
    __shared__ float warpsum[NT / 32];
    __shared__ unsigned int s_ticket;

    int t = threadIdx.x;
    if (t < 64) cm_s[t] = 0u;
    if (t < 8)  cw_s[t] = cw[t];
    __syncthreads();

    float ce = 0.0f;
    int stride = gridDim.x * blockDim.x;
    for (int i = blockIdx.x * blockDim.x + t; i < B; i += stride) {
        // batch all 4 128-bit streaming loads up front (MLP=4, evict-first)
        float4 a0 = __ldcs(&pred[2 * i]);
        float4 a1 = __ldcs(&pred[2 * i + 1]);
        float4 g0 = __ldcs(&gt[2 * i]);
        float4 g1 = __ldcs(&gt[2 * i + 1]);
        float x[8]  = {a0.x, a0.y, a0.z, a0.w, a1.x, a1.y, a1.z, a1.w};
        float gv[8] = {g0.x, g0.y, g0.z, g0.w, g1.x, g1.y, g1.z, g1.w};

        // pred argmax (first-max tie-break = jnp.argmax; softmax is monotone)
        float m = x[0]; int pa = 0;
        #pragma unroll
        for (int j = 1; j < 8; j++) { if (x[j] > m) { m = x[j]; pa = j; } }

        // gt index from one-hot via fma dot with [0..7]
        float fg = gv[1];
        fg = fmaf(2.0f, gv[2], fg);
        fg = fmaf(3.0f, gv[3], fg);
        fg = fmaf(4.0f, gv[4], fg);
        fg = fmaf(5.0f, gv[5], fg);
        fg = fmaf(6.0f, gv[6], fg);
        fg = fmaf(7.0f, gv[7], fg);
        int gi = (int)(fg + 0.5f);

        // softmax without max-shift: x ~ N(0,1), |x| < ~7, EX2 range-safe
        float e[8];
        float S = 0.0f;
        #pragma unroll
        for (int j = 0; j < 8; j++) { e[j] = __expf(x[j]); S += e[j]; }

        float r = __fdividef(1.0f, S);

        // p[gi] via dot with one-hot (no dynamic register indexing)
        float eg = e[0] * gv[0];
        #pragma unroll
        for (int j = 1; j < 8; j++) eg = fmaf(e[j], gv[j], eg);
        float pg = eg * r;

        // S2 = sum_j exp(p_j), p_j in (0,1]
        float S2 = 0.0f;
        #pragma unroll
        for (int j = 0; j < 8; j++) S2 += __expf(e[j] * r);

        float lse2 = __logf(S2);

        ce = fmaf(cw_s[gi], lse2 - pg, ce);
        atomicAdd(&cm_s[gi * 8 + pa], 1u);
    }

    // CE reduction: warp shuffle -> shared -> one double atomic per block
    #pragma unroll
    for (int o = 16; o > 0; o >>= 1) ce += __shfl_down_sync(0xFFFFFFFFu, ce, o);
    if ((t & 31) == 0) warpsum[t >> 5] = ce;
    __syncthreads();
    if (t == 0) {
        double s = 0.0;
        #pragma unroll
        for (int k = 0; k < NT / 32; k++) s += (double)warpsum[k];
        atomicAdd(&g_ce, s);
    }
    if (t < 64) atomicAdd(&g_cm[t], cm_s[t]);

    // Last-block-done finalize (register-lean: no unrolled caches, float math;
    // CM counts <= 2^22 are exact in float).
    __syncthreads();
    if (t == 0) {
        __threadfence();  // make this block's g_ce / g_cm atomics visible
        s_ticket = atomicAdd(&g_done, 1u);
    }
    __syncthreads();

    if (s_ticket == (unsigned)(gridDim.x - 1) && t == 0) {
        float dice_loss = 0.0f;
        #pragma unroll 1
        for (int ii = 0; ii < 8; ii++) {
            float row = 0.0f, col = 0.0f;
            #pragma unroll 1
            for (int j = 0; j < 8; j++) {
                row += (float)(*((volatile unsigned int*)&g_cm[ii * 8 + j]));
                col += (float)(*((volatile unsigned int*)&g_cm[j * 8 + ii]));
            }
            float tp = (float)(*((volatile unsigned int*)&g_cm[ii * 9]));
            float dice = (tp + 1e-8f) / (row + col - tp + 1e-8f);
            dice_loss += (1.0f - dice) * cw_s[ii];
        }
        dice_loss *= 0.125f;
        double ce_tot = *((volatile double*)&g_ce);
        out[0] = (float)(ce_tot * invB + 0.5 * (double)dice_loss);

        // reset state for the next graph replay
        g_ce = 0.0;
        #pragma unroll 1
        for (int k = 0; k < 64; k++) g_cm[k] = 0u;
        __threadfence();
        g_done = 0u;
    }
}

extern "C" void kernel_launch(void* const* d_in, const int* in_sizes, int n_in,
                              void* d_out, int out_size) {
    const float4* pred = (const float4*)d_in[0];
    const float4* gt   = (const float4*)d_in[1];
    const float*  cw   = (const float*)d_in[2];
    float* out = (float*)d_out;
    int B = in_sizes[0] / 8;

    fused_k<<<NB, NT>>>(pred, gt, cw, out, B, 1.0 / (double)B);
}

// round 8
// speedup vs baseline: 1.1724x; 1.0345x over previous
#include <cuda_runtime.h>
#include <cuda_bf16.h>

#define NB 740              // 5 CTAs/SM x 148 SMs: exactly one persistent wave
#define NT 256

// Zero-initialized at module load. The finalizing block resets them to zero
// after each run, so every graph replay starts from a clean state.
__device__ double       g_ce;
__device__ unsigned int g_cm[64];
__device__ unsigned int g_done;

__global__ void __launch_bounds__(NT, 5)   // keep 5 CTAs resident (regs <= 51)
fused_k(const float4* __restrict__ pred, const float4* __restrict__ gt,
        const float* __restrict__ cw, float* __restrict__ out,
        int B, double invB)
{
    __shared__ unsigned int cm_s[64];
    __shared__ float cw_s[8];
    __shared__ float warpsum[NT / 32];
    __shared__ unsigned int s_ticket;

    int t = threadIdx.x;
    if (t < 64) cm_s[t] = 0u;
    if (t < 8)  cw_s[t] = cw[t];
    __syncthreads();

    float ce = 0.0f;
    int stride = gridDim.x * blockDim.x;
    for (int i = blockIdx.x * blockDim.x + t; i < B; i += stride) {
        // batch all 4 128-bit loads up front (MLP=4 per iteration)
        float4 a0 = __ldg(&pred[2 * i]);
        float4 a1 = __ldg(&pred[2 * i + 1]);
        float4 g0 = __ldg(&gt[2 * i]);
        float4 g1 = __ldg(&gt[2 * i + 1]);
        float x[8]  = {a0.x, a0.y, a0.z, a0.w, a1.x, a1.y, a1.z, a1.w};
        float gv[8] = {g0.x, g0.y, g0.z, g0.w, g1.x, g1.y, g1.z, g1.w};

        // pred argmax (first-max tie-break = jnp.argmax; softmax is monotone)
        float m = x[0]; int pa = 0;
        #pragma unroll
        for (int j = 1; j < 8; j++) { if (x[j] > m) { m = x[j]; pa = j; } }

        // gt index from one-hot via fma dot with [0..7]
        float fg = gv[1];
        fg = fmaf(2.0f, gv[2], fg);
        fg = fmaf(3.0f, gv[3], fg);
        fg = fmaf(4.0f, gv[4], fg);
        fg = fmaf(5.0f, gv[5], fg);
        fg = fmaf(6.0f, gv[6], fg);
        fg = fmaf(7.0f, gv[7], fg);
        int gi = (int)(fg + 0.5f);

        // softmax without max-shift: x ~ N(0,1), |x| < ~7, EX2 range-safe
        float e[8];
        float S = 0.0f;
        #pragma unroll
        for (int j = 0; j < 8; j++) { e[j] = __expf(x[j]); S += e[j]; }

        float r = __fdividef(1.0f, S);

        // p[gi] via dot with one-hot (no dynamic register indexing)
        float eg = e[0] * gv[0];
        #pragma unroll
        for (int j = 1; j < 8; j++) eg = fmaf(e[j], gv[j], eg);
        float pg = eg * r;

        // S2 = sum_j exp(p_j), p_j in (0,1]
        float S2 = 0.0f;
        #pragma unroll
        for (int j = 0; j < 8; j++) S2 += __expf(e[j] * r);

        float lse2 = __logf(S2);

        ce = fmaf(cw_s[gi], lse2 - pg, ce);
        atomicAdd(&cm_s[gi * 8 + pa], 1u);
    }

    // CE reduction: warp shuffle -> shared -> one double atomic per block
    #pragma unroll
    for (int o = 16; o > 0; o >>= 1) ce += __shfl_down_sync(0xFFFFFFFFu, ce, o);
    if ((t & 31) == 0) warpsum[t >> 5] = ce;
    __syncthreads();
    if (t == 0) {
        double s = 0.0;
        #pragma unroll
        for (int k = 0; k < NT / 32; k++) s += (double)warpsum[k];
        atomicAdd(&g_ce, s);
    }
    if (t < 64) atomicAdd(&g_cm[t], cm_s[t]);

    // Last-block-done finalize (register-lean; CM counts <= 2^22 exact in float)
    __syncthreads();
    if (t == 0) {
        __threadfence();  // make this block's g_ce / g_cm atomics visible
        s_ticket = atomicAdd(&g_done, 1u);
    }
    __syncthreads();

    if (s_ticket == (unsigned)(gridDim.x - 1) && t == 0) {
        float dice_loss = 0.0f;
        #pragma unroll 1
        for (int ii = 0; ii < 8; ii++) {
            float row = 0.0f, col = 0.0f;
            #pragma unroll 1
            for (int j = 0; j < 8; j++) {
                row += (float)(*((volatile unsigned int*)&g_cm[ii * 8 + j]));
                col += (float)(*((volatile unsigned int*)&g_cm[j * 8 + ii]));
            }
            float tp = (float)(*((volatile unsigned int*)&g_cm[ii * 9]));
            float dice = (tp + 1e-8f) / (row + col - tp + 1e-8f);
            dice_loss += (1.0f - dice) * cw_s[ii];
        }
        dice_loss *= 0.125f;
        double ce_tot = *((volatile double*)&g_ce);
        out[0] = (float)(ce_tot * invB + 0.5 * (double)dice_loss);

        // reset state for the next graph replay
        g_ce = 0.0;
        #pragma unroll 1
        for (int k = 0; k < 64; k++) g_cm[k] = 0u;
        __threadfence();
        g_done = 0u;
    }
}

extern "C" void kernel_launch(void* const* d_in, const int* in_sizes, int n_in,
                              void* d_out, int out_size) {
    const float4* pred = (const float4*)d_in[0];
    const float4* gt   = (const float4*)d_in[1];
    const float*  cw   = (const float*)d_in[2];
    float* out = (float*)d_out;
    int B = in_sizes[0] / 8;

    fused_k<<<NB, NT>>>(pred, gt, cw, out, B, 1.0 / (double)B);
}

// round 9
// speedup vs baseline: 1.4167x; 1.2083x over previous
#include <cuda_runtime.h>
#include <cuda_bf16.h>

#define NB 740              // 5 CTAs/SM x 148 SMs: exactly one persistent wave
#define NT 256

// Zero-initialized at module load. The finalizing block resets them after each
// run, so every graph replay starts from a clean state.
__device__ double       g_ce;
__device__ unsigned int g_row[8];    // count(gt == c)
__device__ unsigned int g_col[8];    // count(pred == c)
__device__ unsigned int g_diag[8];   // count(gt == pred == c)
__device__ unsigned int g_done;

__global__ void __launch_bounds__(NT, 5)   // keep 5 CTAs resident (regs <= 51)
fused_k(const float4* __restrict__ pred, const float4* __restrict__ gt,
        const float* __restrict__ cw, float* __restrict__ out,
        int B, double invB)
{
    __shared__ unsigned int row_s[8], col_s[8], diag_s[8];
    __shared__ float warpsum[NT / 32];
    __shared__ unsigned int s_ticket;

    int t = threadIdx.x;
    if (t < 8) { row_s[t] = 0u; col_s[t] = 0u; diag_s[t] = 0u; }

    // class weights: block-uniform loads -> uniform registers
    float w0 = __ldg(&cw[0]), w1 = __ldg(&cw[1]), w2 = __ldg(&cw[2]), w3 = __ldg(&cw[3]);
    float w4 = __ldg(&cw[4]), w5 = __ldg(&cw[5]), w6 = __ldg(&cw[6]), w7 = __ldg(&cw[7]);
    __syncthreads();

    float ce = 0.0f;
    // packed per-thread histograms: 8-bit fields, classes 0-3 in lo, 4-7 in hi
    unsigned rlo = 0u, rhi = 0u, clo = 0u, chi = 0u, dlo = 0u, dhi = 0u;

    int stride = gridDim.x * blockDim.x;
    for (int i = blockIdx.x * blockDim.x + t; i < B; i += stride) {
        float4 a0 = __ldg(&pred[2 * i]);
        float4 a1 = __ldg(&pred[2 * i + 1]);
        float4 g0 = __ldg(&gt[2 * i]);
        float4 g1 = __ldg(&gt[2 * i + 1]);
        float x[8]  = {a0.x, a0.y, a0.z, a0.w, a1.x, a1.y, a1.z, a1.w};
        float gv[8] = {g0.x, g0.y, g0.z, g0.w, g1.x, g1.y, g1.z, g1.w};

        // pred argmax (first-max tie-break = jnp.argmax; softmax is monotone)
        float m = x[0]; int pa = 0;
        #pragma unroll
        for (int j = 1; j < 8; j++) { if (x[j] > m) { m = x[j]; pa = j; } }

        // gt index via fma dot with [0..7]
        float fg = gv[1];
        fg = fmaf(2.0f, gv[2], fg);
        fg = fmaf(3.0f, gv[3], fg);
        fg = fmaf(4.0f, gv[4], fg);
        fg = fmaf(5.0f, gv[5], fg);
        fg = fmaf(6.0f, gv[6], fg);
        fg = fmaf(7.0f, gv[7], fg);
        int gi = (int)(fg + 0.5f);

        // per-sample weight via dot with one-hot (no LDS, no indexed regs)
        float wg =            w0 * gv[0];
        wg = fmaf(w1, gv[1], wg); wg = fmaf(w2, gv[2], wg);
        wg = fmaf(w3, gv[3], wg); wg = fmaf(w4, gv[4], wg);
        wg = fmaf(w5, gv[5], wg); wg = fmaf(w6, gv[6], wg);
        wg = fmaf(w7, gv[7], wg);

        // softmax without max-shift: x ~ N(0,1), EX2 range-safe
        float e[8];
        float S = 0.0f;
        #pragma unroll
        for (int j = 0; j < 8; j++) { e[j] = __expf(x[j]); S += e[j]; }

        float r = __fdividef(1.0f, S);

        float eg = e[0] * gv[0];
        #pragma unroll
        for (int j = 1; j < 8; j++) eg = fmaf(e[j], gv[j], eg);
        float pg = eg * r;

        float S2 = 0.0f;
        #pragma unroll
        for (int j = 0; j < 8; j++) S2 += __expf(e[j] * r);

        float lse2 = __logf(S2);
        ce = fmaf(wg, lse2 - pg, ce);

        // register histograms (replaces per-sample shared atomic)
        unsigned rinc = 1u << ((gi & 3) << 3);
        if (gi < 4) rlo += rinc; else rhi += rinc;
        unsigned cinc = 1u << ((pa & 3) << 3);
        if (pa < 4) clo += cinc; else chi += cinc;
        if (gi == pa) { if (gi < 4) dlo += rinc; else dhi += rinc; }
    }

    // ---- CE reduction: warp shuffle -> shared -> one double atomic per block
    #pragma unroll
    for (int o = 16; o > 0; o >>= 1) ce += __shfl_down_sync(0xFFFFFFFFu, ce, o);
    if ((t & 31) == 0) warpsum[t >> 5] = ce;

    // ---- histogram flush: 8b->16b field split, REDUX across warp, lane0 atomics
    {
        int lane = t & 31;
        unsigned p[6] = {rlo, rhi, clo, chi, dlo, dhi};
        unsigned int* dsts[3] = {row_s, col_s, diag_s};
        #pragma unroll
        for (int h = 0; h < 3; h++) {
            unsigned lo = p[2 * h], hi = p[2 * h + 1];
            unsigned a = __reduce_add_sync(0xFFFFFFFFu, lo & 0x00FF00FFu);
            unsigned b = __reduce_add_sync(0xFFFFFFFFu, (lo >> 8) & 0x00FF00FFu);
            unsigned c = __reduce_add_sync(0xFFFFFFFFu, hi & 0x00FF00FFu);
            unsigned d = __reduce_add_sync(0xFFFFFFFFu, (hi >> 8) & 0x00FF00FFu);
            if (lane == 0) {
                atomicAdd(&dsts[h][0], a & 0xFFFFu);
                atomicAdd(&dsts[h][2], a >> 16);
                atomicAdd(&dsts[h][1], b & 0xFFFFu);
                atomicAdd(&dsts[h][3], b >> 16);
                atomicAdd(&dsts[h][4], c & 0xFFFFu);
                atomicAdd(&dsts[h][6], c >> 16);
                atomicAdd(&dsts[h][5], d & 0xFFFFu);
                atomicAdd(&dsts[h][7], d >> 16);
            }
        }
    }
    __syncthreads();

    if (t == 0) {
        double s = 0.0;
        #pragma unroll
        for (int k = 0; k < NT / 32; k++) s += (double)warpsum[k];
        atomicAdd(&g_ce, s);
    }
    if (t < 8) {
        atomicAdd(&g_row[t],  row_s[t]);
        atomicAdd(&g_col[t],  col_s[t]);
        atomicAdd(&g_diag[t], diag_s[t]);
    }

    // ---- last-block-done finalize
    __syncthreads();
    if (t == 0) {
        __threadfence();
        s_ticket = atomicAdd(&g_done, 1u);
    }
    __syncthreads();

    if (s_ticket == (unsigned)(gridDim.x - 1) && t == 0) {
        float dice_loss = 0.0f;
        #pragma unroll 1
        for (int ii = 0; ii < 8; ii++) {
            float row = (float)(*((volatile unsigned int*)&g_row[ii]));
            float col = (float)(*((volatile unsigned int*)&g_col[ii]));
            float tp  = (float)(*((volatile unsigned int*)&g_diag[ii]));
            float dice = (tp + 1e-8f) / (row + col - tp + 1e-8f);
            dice_loss += (1.0f - dice) * __ldg(&cw[ii]);
        }
        dice_loss *= 0.125f;
        double ce_tot = *((volatile double*)&g_ce);
        out[0] = (float)(ce_tot * invB + 0.5 * (double)dice_loss);

        // reset state for the next graph replay
        g_ce = 0.0;
        #pragma unroll 1
        for (int k = 0; k < 8; k++) { g_row[k] = 0u; g_col[k] = 0u; g_diag[k] = 0u; }
        __threadfence();
        g_done = 0u;
    }
}

extern "C" void kernel_launch(void* const* d_in, const int* in_sizes, int n_in,
                              void* d_out, int out_size) {
    const float4* pred = (const float4*)d_in[0];
    const float4* gt   = (const float4*)d_in[1];
    const float*  cw   = (const float*)d_in[2];
    float* out = (float*)d_out;
    int B = in_sizes[0] / 8;

    fused_k<<<NB, NT>>>(pred, gt, cw, out, B, 1.0 / (double)B);
}

// round 10
// speedup vs baseline: 1.4232x; 1.0046x over previous
#include <cuda_runtime.h>
#include <cuda_bf16.h>

#define NB 592              // 4 CTAs/SM x 148 SMs: exactly one persistent wave
#define NT 256

// Zero-initialized at module load. The finalizing block resets them after each
// run, so every graph replay starts from a clean state.
__device__ double       g_ce;
__device__ unsigned int g_row[8];    // count(gt == c)
__device__ unsigned int g_col[8];    // count(pred == c)
__device__ unsigned int g_diag[8];   // count(gt == pred == c)
__device__ unsigned int g_done;

__global__ void __launch_bounds__(NT, 4)   // <=64 regs: room for prefetch buffer
fused_k(const float4* __restrict__ pred, const float4* __restrict__ gt,
        const float* __restrict__ cw, float* __restrict__ out,
        int B, double invB)
{
    __shared__ unsigned int row_s[8], col_s[8], diag_s[8];
    __shared__ float warpsum[NT / 32];
    __shared__ unsigned int s_ticket;

    int t = threadIdx.x;
    if (t < 8) { row_s[t] = 0u; col_s[t] = 0u; diag_s[t] = 0u; }

    // class weights: block-uniform loads -> uniform registers
    float w0 = __ldg(&cw[0]), w1 = __ldg(&cw[1]), w2 = __ldg(&cw[2]), w3 = __ldg(&cw[3]);
    float w4 = __ldg(&cw[4]), w5 = __ldg(&cw[5]), w6 = __ldg(&cw[6]), w7 = __ldg(&cw[7]);
    __syncthreads();

    float ce = 0.0f;
    // packed per-thread histograms: 8-bit fields, classes 0-3 in lo, 4-7 in hi
    unsigned rlo = 0u, rhi = 0u, clo = 0u, chi = 0u, dlo = 0u, dhi = 0u;

    int stride = gridDim.x * blockDim.x;
    int i = blockIdx.x * blockDim.x + t;

    // prime the software pipeline
    float4 a0, a1, b0, b1;
    if (i < B) {
        a0 = __ldg(&pred[2 * i]);
        a1 = __ldg(&pred[2 * i + 1]);
        b0 = __ldg(&gt[2 * i]);
        b1 = __ldg(&gt[2 * i + 1]);
    }

    while (i < B) {
        // prefetch next iteration (clamped to current index on the last one:
        // re-load hits L1, costs nothing, keeps the loop branch-free)
        int nx = i + stride;
        int pf = (nx < B) ? nx : i;
        float4 na0 = __ldg(&pred[2 * pf]);
        float4 na1 = __ldg(&pred[2 * pf + 1]);
        float4 nb0 = __ldg(&gt[2 * pf]);
        float4 nb1 = __ldg(&gt[2 * pf + 1]);

        float x[8]  = {a0.x, a0.y, a0.z, a0.w, a1.x, a1.y, a1.z, a1.w};
        float gv[8] = {b0.x, b0.y, b0.z, b0.w, b1.x, b1.y, b1.z, b1.w};

        // pred argmax (first-max tie-break = jnp.argmax; softmax is monotone)
        float m = x[0]; int pa = 0;
        #pragma unroll
        for (int j = 1; j < 8; j++) { if (x[j] > m) { m = x[j]; pa = j; } }

        // gt index via fma dot with [0..7]
        float fg = gv[1];
        fg = fmaf(2.0f, gv[2], fg);
        fg = fmaf(3.0f, gv[3], fg);
        fg = fmaf(4.0f, gv[4], fg);
        fg = fmaf(5.0f, gv[5], fg);
        fg = fmaf(6.0f, gv[6], fg);
        fg = fmaf(7.0f, gv[7], fg);
        int gi = (int)(fg + 0.5f);

        // per-sample weight via dot with one-hot
        float wg =            w0 * gv[0];
        wg = fmaf(w1, gv[1], wg); wg = fmaf(w2, gv[2], wg);
        wg = fmaf(w3, gv[3], wg); wg = fmaf(w4, gv[4], wg);
        wg = fmaf(w5, gv[5], wg); wg = fmaf(w6, gv[6], wg);
        wg = fmaf(w7, gv[7], wg);

        // softmax without max-shift: x ~ N(0,1), EX2 range-safe
        float e[8];
        float S = 0.0f;
        #pragma unroll
        for (int j = 0; j < 8; j++) { e[j] = __expf(x[j]); S += e[j]; }

        float r = __fdividef(1.0f, S);

        float eg = e[0] * gv[0];
        #pragma unroll
        for (int j = 1; j < 8; j++) eg = fmaf(e[j], gv[j], eg);
        float pg = eg * r;

        float S2 = 0.0f;
        #pragma unroll
        for (int j = 0; j < 8; j++) S2 += __expf(e[j] * r);

        float lse2 = __logf(S2);
        ce = fmaf(wg, lse2 - pg, ce);

        // register histograms
        unsigned rinc = 1u << ((gi & 3) << 3);
        if (gi < 4) rlo += rinc; else rhi += rinc;
        unsigned cinc = 1u << ((pa & 3) << 3);
        if (pa < 4) clo += cinc; else chi += cinc;
        if (gi == pa) { if (gi < 4) dlo += rinc; else dhi += rinc; }

        // rotate pipeline
        a0 = na0; a1 = na1; b0 = nb0; b1 = nb1;
        i = nx;
    }

    // ---- CE reduction: warp shuffle -> shared -> one double atomic per block
    #pragma unroll
    for (int o = 16; o > 0; o >>= 1) ce += __shfl_down_sync(0xFFFFFFFFu, ce, o);
    if ((t & 31) == 0) warpsum[t >> 5] = ce;

    // ---- histogram flush: 8b->16b field split, REDUX across warp, lane0 atomics
    {
        int lane = t & 31;
        unsigned p[6] = {rlo, rhi, clo, chi, dlo, dhi};
        unsigned int* dsts[3] = {row_s, col_s, diag_s};
        #pragma unroll
        for (int h = 0; h < 3; h++) {
            unsigned lo = p[2 * h], hi = p[2 * h + 1];
            unsigned a = __reduce_add_sync(0xFFFFFFFFu, lo & 0x00FF00FFu);
            unsigned b = __reduce_add_sync(0xFFFFFFFFu, (lo >> 8) & 0x00FF00FFu);
            unsigned c = __reduce_add_sync(0xFFFFFFFFu, hi & 0x00FF00FFu);
            unsigned d = __reduce_add_sync(0xFFFFFFFFu, (hi >> 8) & 0x00FF00FFu);
            if (lane == 0) {
                atomicAdd(&dsts[h][0], a & 0xFFFFu);
                atomicAdd(&dsts[h][2], a >> 16);
                atomicAdd(&dsts[h][1], b & 0xFFFFu);
                atomicAdd(&dsts[h][3], b >> 16);
                atomicAdd(&dsts[h][4], c & 0xFFFFu);
                atomicAdd(&dsts[h][6], c >> 16);
                atomicAdd(&dsts[h][5], d & 0xFFFFu);
                atomicAdd(&dsts[h][7], d >> 16);
            }
        }
    }
    __syncthreads();

    if (t == 0) {
        double s = 0.0;
        #pragma unroll
        for (int k = 0; k < NT / 32; k++) s += (double)warpsum[k];
        atomicAdd(&g_ce, s);
    }
    if (t < 8) {
        atomicAdd(&g_row[t],  row_s[t]);
        atomicAdd(&g_col[t],  col_s[t]);
        atomicAdd(&g_diag[t], diag_s[t]);
    }

    // ---- last-block-done finalize
    __syncthreads();
    if (t == 0) {
        __threadfence();
        s_ticket = atomicAdd(&g_done, 1u);
    }
    __syncthreads();

    if (s_ticket == (unsigned)(gridDim.x - 1) && t == 0) {
        float dice_loss = 0.0f;
        #pragma unroll 1
        for (int ii = 0; ii < 8; ii++) {
            float row = (float)(*((volatile unsigned int*)&g_row[ii]));
            float col = (float)(*((volatile unsigned int*)&g_col[ii]));
            float tp  = (float)(*((volatile unsigned int*)&g_diag[ii]));
            float dice = (tp + 1e-8f) / (row + col - tp + 1e-8f);
            dice_loss += (1.0f - dice) * __ldg(&cw[ii]);
        }
        dice_loss *= 0.125f;
        double ce_tot = *((volatile double*)&g_ce);
        out[0] = (float)(ce_tot * invB + 0.5 * (double)dice_loss);

        // reset state for the next graph replay
        g_ce = 0.0;
        #pragma unroll 1
        for (int k = 0; k < 8; k++) { g_row[k] = 0u; g_col[k] = 0u; g_diag[k] = 0u; }
        __threadfence();
        g_done = 0u;
    }
}

extern "C" void kernel_launch(void* const* d_in, const int* in_sizes, int n_in,
                              void* d_out, int out_size) {
    const float4* pred = (const float4*)d_in[0];
    const float4* gt   = (const float4*)d_in[1];
    const float*  cw   = (const float*)d_in[2];
    float* out = (float*)d_out;
    int B = in_sizes[0] / 8;

    fused_k<<<NB, NT>>>(pred, gt, cw, out, B, 1.0 / (double)B);
}